// round 14
// baseline (speedup 1.0000x reference)
#include <cuda_runtime.h>
#include <cstdint>

// QuantizedLinear(5 -> 10, bits=2) over 4M tokens, fp32.
//
// 3-stage TMA ring pipeline, 8 tiles of 256 tokens per block: loads for tile
// i+3 issue as soon as tile i's sx buffer is consumed; bulk stores run with
// up to 2 groups in flight (wait_group 2 reclaims the so buffer written 3
// tiles ago). This amortizes DRAM round-trip latency (the round-13 wall)
// across 8 tiles. Compute: thread-pair split (even lane: outputs 0-4, odd:
// 5-9), conflict-free LDS/STS; weights dequantized in-block, fetched as 8
// broadcast LDS.128.

#define THREADS 256
#define TILE 256                  // tokens per tile
#define NT 8                      // tiles per block
#define NS 3                      // pipeline stages
#define IN_F 5
#define OUT_F 10
#define XB (TILE * IN_F * 4)      // 5120 B
#define OB (TILE * OUT_F * 4)     // 10240 B

#define MBAR_WAIT(mbaddr, ph) do {                                          \
    uint32_t _done;                                                         \
    asm volatile(                                                           \
        "{\n\t.reg .pred pq;\n\t"                                           \
        "mbarrier.try_wait.parity.acquire.cta.shared::cta.b64 pq, [%1], %2;\n\t" \
        "selp.b32 %0, 1, 0, pq;\n\t}"                                       \
        : "=r"(_done) : "r"(mbaddr), "r"(ph) : "memory");                   \
    if (!_done) {                                                           \
        asm volatile(                                                       \
            "{\n\t.reg .pred P1;\n\t"                                       \
            "W_%=:\n\t"                                                     \
            "mbarrier.try_wait.parity.acquire.cta.shared::cta.b64 P1, [%0], %1, 0x989680;\n\t" \
            "@P1 bra.uni D_%=;\n\t"                                         \
            "bra.uni W_%=;\n\t"                                             \
            "D_%=:\n\t}"                                                    \
            :: "r"(mbaddr), "r"(ph) : "memory");                            \
    }                                                                       \
} while (0)

__global__ __launch_bounds__(THREADS, 5)
void qlinear2bit_kernel(const float* __restrict__ x,
                        const float* __restrict__ w,
                        const float* __restrict__ bias,
                        float* __restrict__ out,
                        int n_tokens)
{
    __shared__ __align__(128) float sx[NS][TILE * IN_F];    // 3 x 5 KB
    __shared__ __align__(128) float so[NS][TILE * OUT_F];   // 3 x 10 KB
    __shared__ __align__(16)  float swp[2][32];             // padded w+bias
    __shared__ __align__(8)   unsigned long long mbar[NS];

    const int t = threadIdx.x;
    const long long tok0 = (long long)blockIdx.x * (TILE * NT);
    const long long N = n_tokens;

    uint32_t mb[NS];
    #pragma unroll
    for (int s = 0; s < NS; s++)
        mb[s] = (uint32_t)__cvta_generic_to_shared(&mbar[s]);

    // ---- prologue: init mbarriers, issue first NS tile loads ----
    if (t == 0) {
        #pragma unroll
        for (int s = 0; s < NS; s++)
            asm volatile("mbarrier.init.shared.b64 [%0], 1;" :: "r"(mb[s]));
        asm volatile("fence.proxy.async.shared::cta;" ::: "memory");
        #pragma unroll
        for (int k = 0; k < NS; k++) {
            const long long ts = tok0 + (long long)k * TILE;
            if (ts + TILE <= N) {
                const uint32_t dst = (uint32_t)__cvta_generic_to_shared(sx[k]);
                asm volatile("mbarrier.arrive.expect_tx.shared.b64 _, [%0], %1;"
                             :: "r"(mb[k]), "r"((uint32_t)XB));
                asm volatile(
                    "cp.async.bulk.shared::cluster.global.mbarrier::complete_tx::bytes "
                    "[%0], [%1], %2, [%3];"
                    :: "r"(dst), "l"(x + ts * IN_F), "r"((uint32_t)XB), "r"(mb[k])
                    : "memory");
            }
        }
    }

    // ---- dequantize weights into padded smem (overlaps prologue loads) ----
    if (t < OUT_F) {
        float r[IN_F];
        float m = 0.0f;
        #pragma unroll
        for (int c = 0; c < IN_F; c++) {
            r[c] = w[t * IN_F + c];
            m = fmaxf(m, fabsf(r[c]));
        }
        float scale = fmaxf(m, 1e-8f);          // qmax = 2^(bits-1)-1 = 1
        float inv = 1.0f / scale;
        const int hh = t / 5, jj = t % 5;
        #pragma unroll
        for (int c = 0; c < IN_F; c++) {
            float q = rintf(r[c] * inv);        // round-half-to-even == jnp.round
            swp[hh][jj * IN_F + c] = fminf(fmaxf(q, -2.0f), 1.0f) * scale;
        }
        swp[hh][25 + jj] = bias[t];
    } else if (t >= OUT_F && t < 14) {          // zero pads for LDS.128
        const int i = t - OUT_F;
        swp[i >> 1][30 + (i & 1)] = 0.0f;
    }
    __syncthreads();    // mbarrier inits + swp visible

    // ---- per-thread weights: 8 broadcast LDS.128 ----
    const int p = t >> 1;       // pair/token index (0..127)
    const int h = t & 1;        // output rows h*5 .. h*5+4
    float wr[32];
    #pragma unroll
    for (int i = 0; i < 8; i++)
        ((float4*)wr)[i] = ((const float4*)swp[h])[i];

    // ---- pipelined main loop ----
    for (int i = 0; i < NT; i++) {
        const long long ts = tok0 + (long long)i * TILE;
        if (ts >= N) break;
        const int s = i % NS;
        const uint32_t ph = (uint32_t)((i / NS) & 1);
        const bool full = (ts + TILE <= N);

        if (full) {
            MBAR_WAIT(mb[s], ph);               // x tile i ready
            if (t == 0 && i >= NS) {
                // reclaim so[s]: store issued 3 tiles ago must be done
                asm volatile("cp.async.bulk.wait_group 2;" ::: "memory");
            }
            __syncthreads();                    // buffer-free visible to all

            // compute 256 tokens (2 passes, pair shares a token)
            #pragma unroll
            for (int q2 = 0; q2 < 2; q2++) {
                const int tok = p + q2 * 128;
                float xi[IN_F];
                #pragma unroll
                for (int c = 0; c < IN_F; c++)
                    xi[c] = sx[s][tok * IN_F + c];        // pair-multicast
                #pragma unroll
                for (int j = 0; j < 5; j++) {
                    float acc = wr[25 + j];
                    #pragma unroll
                    for (int c = 0; c < IN_F; c++)
                        acc = fmaf(xi[c], wr[j * IN_F + c], acc);
                    so[s][tok * OUT_F + h * 5 + j] = acc;  // conflict-free
                }
            }
            __syncthreads();                    // all STS done; sx[s] consumed

            if (t == 0) {
                asm volatile("fence.proxy.async.shared::cta;" ::: "memory");
                const uint32_t src = (uint32_t)__cvta_generic_to_shared(so[s]);
                asm volatile(
                    "cp.async.bulk.global.shared::cta.bulk_group [%0], [%1], %2;"
                    :: "l"(out + ts * OUT_F), "r"(src), "r"((uint32_t)OB)
                    : "memory");
                asm volatile("cp.async.bulk.commit_group;" ::: "memory");

                // prefetch tile i+NS into the just-freed sx[s]
                const long long nts = tok0 + (long long)(i + NS) * TILE;
                if (i + NS < NT && nts + TILE <= N) {
                    const uint32_t dst =
                        (uint32_t)__cvta_generic_to_shared(sx[s]);
                    asm volatile("mbarrier.arrive.expect_tx.shared.b64 _, [%0], %1;"
                                 :: "r"(mb[s]), "r"((uint32_t)XB));
                    asm volatile(
                        "cp.async.bulk.shared::cluster.global.mbarrier::complete_tx::bytes "
                        "[%0], [%1], %2, [%3];"
                        :: "r"(dst), "l"(x + nts * IN_F), "r"((uint32_t)XB),
                           "r"(mb[s])
                        : "memory");
                }
            }
        } else {
            // partial tile: direct gmem path (tiny tail, no pipeline)
            #pragma unroll
            for (int q2 = 0; q2 < 2; q2++) {
                const long long gtok = ts + p + q2 * 128;
                if (gtok < N) {
                    float xi[IN_F];
                    #pragma unroll
                    for (int c = 0; c < IN_F; c++)
                        xi[c] = x[gtok * IN_F + c];
                    #pragma unroll
                    for (int j = 0; j < 5; j++) {
                        float acc = wr[25 + j];
                        #pragma unroll
                        for (int c = 0; c < IN_F; c++)
                            acc = fmaf(xi[c], wr[j * IN_F + c], acc);
                        out[gtok * OUT_F + h * 5 + j] = acc;
                    }
                }
            }
        }
    }

    // drain: smem must stay alive until all bulk stores have read it
    if (t == 0) {
        asm volatile("cp.async.bulk.wait_group 0;" ::: "memory");
    }
    __syncthreads();
}

extern "C" void kernel_launch(void* const* d_in, const int* in_sizes, int n_in,
                              void* d_out, int out_size)
{
    const float* x    = (const float*)d_in[0];   // [N, 5]
    const float* w    = (const float*)d_in[1];   // [10, 5]
    const float* bias = (const float*)d_in[2];   // [10]
    float* out = (float*)d_out;                  // [N, 10]

    const int n_tokens = in_sizes[0] / IN_F;
    const int tokens_per_block = TILE * NT;
    const int grid = (n_tokens + tokens_per_block - 1) / tokens_per_block;
    qlinear2bit_kernel<<<grid, THREADS>>>(x, w, bias, out, n_tokens);
}